// round 5
// baseline (speedup 1.0000x reference)
#include <cuda_runtime.h>

#define D_MODEL   1024
#define NUM_HEADS 16
#define HEAD_DIM  64
#define BATCH     4
#define SEQ       2048
#define MTOT      (BATCH * SEQ)

// Scratch (allocation-free: __device__ globals). 4 x 32 MB.
__device__ float g_Q [MTOT * D_MODEL];
__device__ float g_K [MTOT * D_MODEL];
__device__ float g_V [MTOT * D_MODEL];
__device__ float g_AO[MTOT * D_MODEL];

// ---------------------------------------------------------------------------
// GEMM (NT): C[M,N] = A[M,K] @ W[N,K]^T + bias[N]    (unchanged from R2;
// measured at ~38 TF/s fp32 = FFMA roofline)
// ---------------------------------------------------------------------------
template <bool SCATTER>
__global__ __launch_bounds__(256)
void gemm_nt_kernel(const float* __restrict__ A, const float* __restrict__ W,
                    const float* __restrict__ bias, float* __restrict__ C)
{
    const int K = D_MODEL;
    __shared__ float As[8][128];
    __shared__ float Ws[8][128];

    const int tid = threadIdx.x;
    const int tx  = tid & 15;
    const int ty  = tid >> 4;
    const int m0  = blockIdx.y * 128;
    const int n0  = blockIdx.x * 128;

    const int lrow = tid >> 1;
    const int lcol = (tid & 1) * 4;
    const float* aptr = A + (size_t)(m0 + lrow) * K + lcol;
    const float* wptr = W + (size_t)(n0 + lrow) * K + lcol;

    float acc[8][8];
#pragma unroll
    for (int i = 0; i < 8; i++)
#pragma unroll
        for (int j = 0; j < 8; j++) acc[i][j] = 0.f;

    float4 av = *(const float4*)(aptr);
    float4 wv = *(const float4*)(wptr);

    for (int k0 = 0; k0 < K; k0 += 8) {
        __syncthreads();
        As[lcol + 0][lrow] = av.x; As[lcol + 1][lrow] = av.y;
        As[lcol + 2][lrow] = av.z; As[lcol + 3][lrow] = av.w;
        Ws[lcol + 0][lrow] = wv.x; Ws[lcol + 1][lrow] = wv.y;
        Ws[lcol + 2][lrow] = wv.z; Ws[lcol + 3][lrow] = wv.w;
        __syncthreads();

        if (k0 + 8 < K) {
            av = *(const float4*)(aptr + k0 + 8);
            wv = *(const float4*)(wptr + k0 + 8);
        }

#pragma unroll
        for (int k = 0; k < 8; k++) {
            float a[8], w[8];
            *(float4*)(a)     = *(const float4*)&As[k][ty * 8];
            *(float4*)(a + 4) = *(const float4*)&As[k][ty * 8 + 4];
            *(float4*)(w)     = *(const float4*)&Ws[k][tx * 8];
            *(float4*)(w + 4) = *(const float4*)&Ws[k][tx * 8 + 4];
#pragma unroll
            for (int i = 0; i < 8; i++)
#pragma unroll
                for (int j = 0; j < 8; j++)
                    acc[i][j] = fmaf(a[i], w[j], acc[i][j]);
        }
    }

    float bi[8];
#pragma unroll
    for (int j = 0; j < 8; j++) bi[j] = bias[n0 + tx * 8 + j];

#pragma unroll
    for (int i = 0; i < 8; i++) {
        const int m = m0 + ty * 8 + i;
#pragma unroll
        for (int jj = 0; jj < 8; jj += 4) {
            const int n = n0 + tx * 8 + jj;
            float4 v;
            v.x = acc[i][jj + 0] + bi[jj + 0];
            v.y = acc[i][jj + 1] + bi[jj + 1];
            v.z = acc[i][jj + 2] + bi[jj + 2];
            v.w = acc[i][jj + 3] + bi[jj + 3];
            if (SCATTER) {
                const int b  = m >> 11;
                const int s  = m & (SEQ - 1);
                const int h  = n >> 6;
                const int hd = n & 63;
                *(float4*)(C + ((size_t)((b * NUM_HEADS + h) * SEQ + s)) * HEAD_DIM + hd) = v;
            } else {
                *(float4*)(C + (size_t)m * D_MODEL + n) = v;
            }
        }
    }
}

// ---------------------------------------------------------------------------
// Flash attention v2, fp32. Br = Bc = 128, Hd = 64, 256 threads.
// QK^T: 8x8 micro-tile (0.5 B smem / FLOP), K held TRANSPOSED in smem
// (Kt[k][n], stride 132) so K-fragment loads are contiguous float4 and Q
// fragment loads are pure broadcasts -> conflict-free.
// PV: 8 rows x 4 cols per thread; P staged via smem (broadcast reads).
// Online softmax over the 16-lane tx group (xor 1,2,4,8 stay in-group).
// ---------------------------------------------------------------------------
#define QS_STRIDE 68
#define KT_STRIDE 132
#define FA_SMEM ((128*QS_STRIDE + 64*KT_STRIDE + 128*64 + 128*128) * 4)

__global__ __launch_bounds__(256, 1)
void flash_attn_kernel(const float* __restrict__ Q, const float* __restrict__ K,
                       const float* __restrict__ V, float* __restrict__ AO)
{
    extern __shared__ float sm[];
    float* Qs = sm;                                   // [128][68]
    float* Kt = Qs + 128 * QS_STRIDE;                 // [64][132] (transposed)
    float* Vs = Kt + 64 * KT_STRIDE;                  // [128][64]
    float* Ps = Vs + 128 * 64;                        // [128][128]

    const int tid = threadIdx.x;
    const int tx  = tid & 15;
    const int ty  = tid >> 4;
    const int bh  = blockIdx.y;
    const int q0  = blockIdx.x * 128;
    const float scale = 0.125f;                       // HEAD_DIM^-0.5

    const float* Qb = Q + (size_t)bh * SEQ * HEAD_DIM;
    const float* Kb = K + (size_t)bh * SEQ * HEAD_DIM;
    const float* Vb = V + (size_t)bh * SEQ * HEAD_DIM;

    // Load Q tile (128x64), pre-scaled. 2048 float4 slots / 256 threads.
#pragma unroll
    for (int it = 0; it < 8; it++) {
        int idx = tid + it * 256;
        int r   = idx >> 4;
        int c4  = (idx & 15) * 4;
        float4 qv = *(const float4*)(Qb + (size_t)(q0 + r) * HEAD_DIM + c4);
        qv.x *= scale; qv.y *= scale; qv.z *= scale; qv.w *= scale;
        *(float4*)&Qs[r * QS_STRIDE + c4] = qv;
    }

    float m_r[8], l_r[8], o[8][4];
#pragma unroll
    for (int i = 0; i < 8; i++) {
        m_r[i] = -1e30f; l_r[i] = 0.f;
#pragma unroll
        for (int j = 0; j < 4; j++) o[i][j] = 0.f;
    }

    for (int kv0 = 0; kv0 < SEQ; kv0 += 128) {
        __syncthreads();   // previous iter's PV reads done before overwrite
        // K: load + transpose into Kt[k][n]; V: straight copy.
#pragma unroll
        for (int it = 0; it < 8; it++) {
            int idx = tid + it * 256;
            int r   = idx >> 4;           // 0..127 (kv row within tile)
            int c4  = (idx & 15) * 4;     // 0..60  (head-dim)
            float4 kv4 = *(const float4*)(Kb + (size_t)(kv0 + r) * HEAD_DIM + c4);
            Kt[(c4 + 0) * KT_STRIDE + r] = kv4.x;
            Kt[(c4 + 1) * KT_STRIDE + r] = kv4.y;
            Kt[(c4 + 2) * KT_STRIDE + r] = kv4.z;
            Kt[(c4 + 3) * KT_STRIDE + r] = kv4.w;
            *(float4*)&Vs[r * 64 + c4] =
                *(const float4*)(Vb + (size_t)(kv0 + r) * HEAD_DIM + c4);
        }
        __syncthreads();

        // ---- S = Q K^T : 8x8 per thread over a 128x128 tile ----
        float s[8][8];
#pragma unroll
        for (int i = 0; i < 8; i++)
#pragma unroll
            for (int j = 0; j < 8; j++) s[i][j] = 0.f;

        for (int k = 0; k < 64; k += 4) {
            float qf[8][4];
#pragma unroll
            for (int i = 0; i < 8; i++)       // broadcast loads
                *(float4*)qf[i] = *(const float4*)&Qs[(ty * 8 + i) * QS_STRIDE + k];
#pragma unroll
            for (int kk = 0; kk < 4; kk++) {
                float kf[8];
                *(float4*)(kf)     = *(const float4*)&Kt[(k + kk) * KT_STRIDE + tx * 8];
                *(float4*)(kf + 4) = *(const float4*)&Kt[(k + kk) * KT_STRIDE + tx * 8 + 4];
#pragma unroll
                for (int i = 0; i < 8; i++)
#pragma unroll
                    for (int j = 0; j < 8; j++)
                        s[i][j] = fmaf(qf[i][kk], kf[j], s[i][j]);
            }
        }

        // ---- online softmax + stage P ----
#pragma unroll
        for (int i = 0; i < 8; i++) {
            float rm = s[i][0];
#pragma unroll
            for (int j = 1; j < 8; j++) rm = fmaxf(rm, s[i][j]);
            rm = fmaxf(rm, __shfl_xor_sync(0xffffffffu, rm, 8));
            rm = fmaxf(rm, __shfl_xor_sync(0xffffffffu, rm, 4));
            rm = fmaxf(rm, __shfl_xor_sync(0xffffffffu, rm, 2));
            rm = fmaxf(rm, __shfl_xor_sync(0xffffffffu, rm, 1));
            float mn    = fmaxf(m_r[i], rm);
            float alpha = __expf(m_r[i] - mn);
            m_r[i] = mn;
            float rs = 0.f;
#pragma unroll
            for (int j = 0; j < 8; j++) {
                s[i][j] = __expf(s[i][j] - mn);
                rs += s[i][j];
            }
            rs += __shfl_xor_sync(0xffffffffu, rs, 8);
            rs += __shfl_xor_sync(0xffffffffu, rs, 4);
            rs += __shfl_xor_sync(0xffffffffu, rs, 2);
            rs += __shfl_xor_sync(0xffffffffu, rs, 1);
            l_r[i] = l_r[i] * alpha + rs;
#pragma unroll
            for (int j = 0; j < 4; j++) o[i][j] *= alpha;
            *(float4*)&Ps[(ty * 8 + i) * 128 + tx * 8] =
                make_float4(s[i][0], s[i][1], s[i][2], s[i][3]);
            *(float4*)&Ps[(ty * 8 + i) * 128 + tx * 8 + 4] =
                make_float4(s[i][4], s[i][5], s[i][6], s[i][7]);
        }
        __syncthreads();

        // ---- O += P V : thread = 8 rows (ty*8+i) x 4 cols (tx*4) ----
        for (int c = 0; c < 128; c += 4) {
            float pf[8][4];
#pragma unroll
            for (int i = 0; i < 8; i++)       // broadcast loads
                *(float4*)pf[i] = *(const float4*)&Ps[(ty * 8 + i) * 128 + c];
#pragma unroll
            for (int cc = 0; cc < 4; cc++) {
                float4 vv = *(const float4*)&Vs[(c + cc) * 64 + tx * 4];
#pragma unroll
                for (int i = 0; i < 8; i++) {
                    o[i][0] = fmaf(pf[i][cc], vv.x, o[i][0]);
                    o[i][1] = fmaf(pf[i][cc], vv.y, o[i][1]);
                    o[i][2] = fmaf(pf[i][cc], vv.z, o[i][2]);
                    o[i][3] = fmaf(pf[i][cc], vv.w, o[i][3]);
                }
            }
        }
    }

    // Epilogue: normalize, write [B,S,D] layout
    const int b = bh >> 4;
    const int h = bh & 15;
#pragma unroll
    for (int i = 0; i < 8; i++) {
        const float inv  = 1.0f / l_r[i];
        const int   srow = q0 + ty * 8 + i;
        float4 ov = make_float4(o[i][0] * inv, o[i][1] * inv,
                                o[i][2] * inv, o[i][3] * inv);
        *(float4*)(AO + ((size_t)(b * SEQ + srow)) * D_MODEL + h * HEAD_DIM + tx * 4) = ov;
    }
}

// ---------------------------------------------------------------------------
extern "C" void kernel_launch(void* const* d_in, const int* in_sizes, int n_in,
                              void* d_out, int out_size)
{
    const float* x  = (const float*)d_in[0];
    const float* wq = (const float*)d_in[1];
    const float* bq = (const float*)d_in[2];
    const float* wk = (const float*)d_in[3];
    const float* bk = (const float*)d_in[4];
    const float* wv = (const float*)d_in[5];
    const float* bv = (const float*)d_in[6];
    const float* wo = (const float*)d_in[7];
    const float* bo = (const float*)d_in[8];

    float *Qp, *Kp, *Vp, *AOp;
    cudaGetSymbolAddress((void**)&Qp,  g_Q);
    cudaGetSymbolAddress((void**)&Kp,  g_K);
    cudaGetSymbolAddress((void**)&Vp,  g_V);
    cudaGetSymbolAddress((void**)&AOp, g_AO);

    const dim3 pg(D_MODEL / 128, MTOT / 128);   // (8, 64)

    gemm_nt_kernel<true><<<pg, 256>>>(x, wq, bq, Qp);
    gemm_nt_kernel<true><<<pg, 256>>>(x, wk, bk, Kp);
    gemm_nt_kernel<true><<<pg, 256>>>(x, wv, bv, Vp);

    cudaFuncSetAttribute(flash_attn_kernel,
                         cudaFuncAttributeMaxDynamicSharedMemorySize, FA_SMEM);
    flash_attn_kernel<<<dim3(SEQ / 128, BATCH * NUM_HEADS), 256, FA_SMEM>>>(Qp, Kp, Vp, AOp);

    gemm_nt_kernel<false><<<pg, 256>>>(AOp, wo, bo, (float*)d_out);
}

// round 6
// speedup vs baseline: 1.4611x; 1.4611x over previous
#include <cuda_runtime.h>

#define D_MODEL   1024
#define NUM_HEADS 16
#define HEAD_DIM  64
#define BATCH     4
#define SEQ       2048
#define MTOT      (BATCH * SEQ)

// Scratch (allocation-free: __device__ globals). 4 x 32 MB.
__device__ float g_Q [MTOT * D_MODEL];
__device__ float g_K [MTOT * D_MODEL];
__device__ float g_V [MTOT * D_MODEL];
__device__ float g_AO[MTOT * D_MODEL];

// ---------------------------------------------------------------------------
// tf32 tensor-core GEMM (NT): C[M,N] = A[M,K] @ W[N,K]^T + bias[N]
// A row-major [M,K], W row-major [N,K] — both K-major, maps directly onto
// mma.sync.aligned.m16n8k8.row.col.f32.tf32.tf32.f32.
//
// Block tile 128x128, BK=32, 256 threads = 8 warps as 2(m) x 4(n),
// warp tile 64x32 = 4x4 m16n8 mma tiles.
// Smem tiles stored with stride 36 words (36 mod 32 == 4) so fragment loads
// hit banks 4*groupID + tig  -> all 32 lanes distinct -> conflict-free.
// cvt.rna.tf32.f32 applied at smem-store time (round-to-nearest).
// ---------------------------------------------------------------------------
#define GS 36   // smem row stride (words) for 32 k-columns

__device__ __forceinline__ unsigned f2tf32(float x) {
    unsigned u;
    asm("cvt.rna.tf32.f32 %0, %1;" : "=r"(u) : "f"(x));
    return u;
}

__device__ __forceinline__ void mma_tf32(float c[4], const unsigned a[4],
                                         const unsigned b[2]) {
    asm volatile(
        "mma.sync.aligned.m16n8k8.row.col.f32.tf32.tf32.f32 "
        "{%0,%1,%2,%3}, {%4,%5,%6,%7}, {%8,%9}, {%0,%1,%2,%3};"
        : "+f"(c[0]), "+f"(c[1]), "+f"(c[2]), "+f"(c[3])
        : "r"(a[0]), "r"(a[1]), "r"(a[2]), "r"(a[3]), "r"(b[0]), "r"(b[1]));
}

template <bool SCATTER>
__global__ __launch_bounds__(256)
void gemm_tf32_kernel(const float* __restrict__ A, const float* __restrict__ W,
                      const float* __restrict__ bias, float* __restrict__ C)
{
    const int K = D_MODEL;
    __shared__ unsigned As[128 * GS];
    __shared__ unsigned Ws[128 * GS];

    const int tid    = threadIdx.x;
    const int wid    = tid >> 5;
    const int lane   = tid & 31;
    const int gid    = lane >> 2;        // groupID 0..7
    const int tig    = lane & 3;         // thread-in-group 0..3
    const int warp_m = wid >> 2;         // 0..1  -> +64 rows
    const int warp_n = wid & 3;          // 0..3  -> +32 cols
    const int m0     = blockIdx.y * 128;
    const int n0     = blockIdx.x * 128;

    // global staging: each thread owns one row-half (16 floats = 4 float4)
    const int grow = tid >> 1;            // 0..127
    const int gcol = (tid & 1) * 16;      // 0 or 16
    const float* aptr = A + (size_t)(m0 + grow) * K + gcol;
    const float* wptr = W + (size_t)(n0 + grow) * K + gcol;

    float acc[4][4][4];
#pragma unroll
    for (int i = 0; i < 4; i++)
#pragma unroll
        for (int j = 0; j < 4; j++)
#pragma unroll
            for (int r = 0; r < 4; r++) acc[i][j][r] = 0.f;

    float4 avr[4], wvr[4];
#pragma unroll
    for (int i = 0; i < 4; i++) {
        avr[i] = *(const float4*)(aptr + i * 4);
        wvr[i] = *(const float4*)(wptr + i * 4);
    }

    for (int k0 = 0; k0 < K; k0 += 32) {
        __syncthreads();
#pragma unroll
        for (int i = 0; i < 4; i++) {
            const int c = gcol + i * 4;
            As[grow * GS + c + 0] = f2tf32(avr[i].x);
            As[grow * GS + c + 1] = f2tf32(avr[i].y);
            As[grow * GS + c + 2] = f2tf32(avr[i].z);
            As[grow * GS + c + 3] = f2tf32(avr[i].w);
            Ws[grow * GS + c + 0] = f2tf32(wvr[i].x);
            Ws[grow * GS + c + 1] = f2tf32(wvr[i].y);
            Ws[grow * GS + c + 2] = f2tf32(wvr[i].z);
            Ws[grow * GS + c + 3] = f2tf32(wvr[i].w);
        }
        __syncthreads();

        if (k0 + 32 < K) {     // prefetch next K-tile into registers
#pragma unroll
            for (int i = 0; i < 4; i++) {
                avr[i] = *(const float4*)(aptr + k0 + 32 + i * 4);
                wvr[i] = *(const float4*)(wptr + k0 + 32 + i * 4);
            }
        }

#pragma unroll
        for (int k8 = 0; k8 < 4; k8++) {
            const int kk = k8 * 8;
            unsigned a[4][4], b[4][2];
#pragma unroll
            for (int mt = 0; mt < 4; mt++) {
                const int m = warp_m * 64 + mt * 16 + gid;
                a[mt][0] = As[(m)     * GS + kk + tig];
                a[mt][1] = As[(m + 8) * GS + kk + tig];
                a[mt][2] = As[(m)     * GS + kk + tig + 4];
                a[mt][3] = As[(m + 8) * GS + kk + tig + 4];
            }
#pragma unroll
            for (int nt = 0; nt < 4; nt++) {
                const int n = warp_n * 32 + nt * 8 + gid;
                b[nt][0] = Ws[n * GS + kk + tig];
                b[nt][1] = Ws[n * GS + kk + tig + 4];
            }
#pragma unroll
            for (int mt = 0; mt < 4; mt++)
#pragma unroll
                for (int nt = 0; nt < 4; nt++)
                    mma_tf32(acc[mt][nt], a[mt], b[nt]);
        }
    }

    // Epilogue: c0/c1 -> (m, n..n+1), c2/c3 -> (m+8, n..n+1)
#pragma unroll
    for (int nt = 0; nt < 4; nt++) {
        const int n  = n0 + warp_n * 32 + nt * 8 + tig * 2;
        const float b0 = bias[n], b1 = bias[n + 1];
#pragma unroll
        for (int mt = 0; mt < 4; mt++) {
            const int m = m0 + warp_m * 64 + mt * 16 + gid;
            float2 v0 = make_float2(acc[mt][nt][0] + b0, acc[mt][nt][1] + b1);
            float2 v1 = make_float2(acc[mt][nt][2] + b0, acc[mt][nt][3] + b1);
            if (SCATTER) {
                // y[m,n] -> [B,H,S,Hd]; n even, n+1 in same head block
                const int h  = n >> 6;
                const int hd = n & 63;
                const int bb = m >> 11;
                const int s  = m & (SEQ - 1);
                float* p0 = C + ((size_t)((bb * NUM_HEADS + h) * SEQ + s))       * HEAD_DIM + hd;
                float* p1 = C + ((size_t)((bb * NUM_HEADS + h) * SEQ + s + 8))   * HEAD_DIM + hd;
                *(float2*)p0 = v0;
                *(float2*)p1 = v1;
            } else {
                *(float2*)(C + (size_t)m * D_MODEL + n)       = v0;
                *(float2*)(C + (size_t)(m + 8) * D_MODEL + n) = v1;
            }
        }
    }
}

// ---------------------------------------------------------------------------
// Flash attention v2, fp32 (unchanged from R4: fma-bound at 53%, 1.71 ms).
// ---------------------------------------------------------------------------
#define QS_STRIDE 68
#define KT_STRIDE 132
#define FA_SMEM ((128*QS_STRIDE + 64*KT_STRIDE + 128*64 + 128*128) * 4)

__global__ __launch_bounds__(256, 1)
void flash_attn_kernel(const float* __restrict__ Q, const float* __restrict__ K,
                       const float* __restrict__ V, float* __restrict__ AO)
{
    extern __shared__ float sm[];
    float* Qs = sm;                                   // [128][68]
    float* Kt = Qs + 128 * QS_STRIDE;                 // [64][132] (transposed)
    float* Vs = Kt + 64 * KT_STRIDE;                  // [128][64]
    float* Ps = Vs + 128 * 64;                        // [128][128]

    const int tid = threadIdx.x;
    const int tx  = tid & 15;
    const int ty  = tid >> 4;
    const int bh  = blockIdx.y;
    const int q0  = blockIdx.x * 128;
    const float scale = 0.125f;

    const float* Qb = Q + (size_t)bh * SEQ * HEAD_DIM;
    const float* Kb = K + (size_t)bh * SEQ * HEAD_DIM;
    const float* Vb = V + (size_t)bh * SEQ * HEAD_DIM;

#pragma unroll
    for (int it = 0; it < 8; it++) {
        int idx = tid + it * 256;
        int r   = idx >> 4;
        int c4  = (idx & 15) * 4;
        float4 qv = *(const float4*)(Qb + (size_t)(q0 + r) * HEAD_DIM + c4);
        qv.x *= scale; qv.y *= scale; qv.z *= scale; qv.w *= scale;
        *(float4*)&Qs[r * QS_STRIDE + c4] = qv;
    }

    float m_r[8], l_r[8], o[8][4];
#pragma unroll
    for (int i = 0; i < 8; i++) {
        m_r[i] = -1e30f; l_r[i] = 0.f;
#pragma unroll
        for (int j = 0; j < 4; j++) o[i][j] = 0.f;
    }

    for (int kv0 = 0; kv0 < SEQ; kv0 += 128) {
        __syncthreads();
#pragma unroll
        for (int it = 0; it < 8; it++) {
            int idx = tid + it * 256;
            int r   = idx >> 4;
            int c4  = (idx & 15) * 4;
            float4 kv4 = *(const float4*)(Kb + (size_t)(kv0 + r) * HEAD_DIM + c4);
            Kt[(c4 + 0) * KT_STRIDE + r] = kv4.x;
            Kt[(c4 + 1) * KT_STRIDE + r] = kv4.y;
            Kt[(c4 + 2) * KT_STRIDE + r] = kv4.z;
            Kt[(c4 + 3) * KT_STRIDE + r] = kv4.w;
            *(float4*)&Vs[r * 64 + c4] =
                *(const float4*)(Vb + (size_t)(kv0 + r) * HEAD_DIM + c4);
        }
        __syncthreads();

        float s[8][8];
#pragma unroll
        for (int i = 0; i < 8; i++)
#pragma unroll
            for (int j = 0; j < 8; j++) s[i][j] = 0.f;

        for (int k = 0; k < 64; k += 4) {
            float qf[8][4];
#pragma unroll
            for (int i = 0; i < 8; i++)
                *(float4*)qf[i] = *(const float4*)&Qs[(ty * 8 + i) * QS_STRIDE + k];
#pragma unroll
            for (int kk = 0; kk < 4; kk++) {
                float kf[8];
                *(float4*)(kf)     = *(const float4*)&Kt[(k + kk) * KT_STRIDE + tx * 8];
                *(float4*)(kf + 4) = *(const float4*)&Kt[(k + kk) * KT_STRIDE + tx * 8 + 4];
#pragma unroll
                for (int i = 0; i < 8; i++)
#pragma unroll
                    for (int j = 0; j < 8; j++)
                        s[i][j] = fmaf(qf[i][kk], kf[j], s[i][j]);
            }
        }

#pragma unroll
        for (int i = 0; i < 8; i++) {
            float rm = s[i][0];
#pragma unroll
            for (int j = 1; j < 8; j++) rm = fmaxf(rm, s[i][j]);
            rm = fmaxf(rm, __shfl_xor_sync(0xffffffffu, rm, 8));
            rm = fmaxf(rm, __shfl_xor_sync(0xffffffffu, rm, 4));
            rm = fmaxf(rm, __shfl_xor_sync(0xffffffffu, rm, 2));
            rm = fmaxf(rm, __shfl_xor_sync(0xffffffffu, rm, 1));
            float mn    = fmaxf(m_r[i], rm);
            float alpha = __expf(m_r[i] - mn);
            m_r[i] = mn;
            float rs = 0.f;
#pragma unroll
            for (int j = 0; j < 8; j++) {
                s[i][j] = __expf(s[i][j] - mn);
                rs += s[i][j];
            }
            rs += __shfl_xor_sync(0xffffffffu, rs, 8);
            rs += __shfl_xor_sync(0xffffffffu, rs, 4);
            rs += __shfl_xor_sync(0xffffffffu, rs, 2);
            rs += __shfl_xor_sync(0xffffffffu, rs, 1);
            l_r[i] = l_r[i] * alpha + rs;
#pragma unroll
            for (int j = 0; j < 4; j++) o[i][j] *= alpha;
            *(float4*)&Ps[(ty * 8 + i) * 128 + tx * 8] =
                make_float4(s[i][0], s[i][1], s[i][2], s[i][3]);
            *(float4*)&Ps[(ty * 8 + i) * 128 + tx * 8 + 4] =
                make_float4(s[i][4], s[i][5], s[i][6], s[i][7]);
        }
        __syncthreads();

        for (int c = 0; c < 128; c += 4) {
            float pf[8][4];
#pragma unroll
            for (int i = 0; i < 8; i++)
                *(float4*)pf[i] = *(const float4*)&Ps[(ty * 8 + i) * 128 + c];
#pragma unroll
            for (int cc = 0; cc < 4; cc++) {
                float4 vv = *(const float4*)&Vs[(c + cc) * 64 + tx * 4];
#pragma unroll
                for (int i = 0; i < 8; i++) {
                    o[i][0] = fmaf(pf[i][cc], vv.x, o[i][0]);
                    o[i][1] = fmaf(pf[i][cc], vv.y, o[i][1]);
                    o[i][2] = fmaf(pf[i][cc], vv.z, o[i][2]);
                    o[i][3] = fmaf(pf[i][cc], vv.w, o[i][3]);
                }
            }
        }
    }

    const int b = bh >> 4;
    const int h = bh & 15;
#pragma unroll
    for (int i = 0; i < 8; i++) {
        const float inv  = 1.0f / l_r[i];
        const int   srow = q0 + ty * 8 + i;
        float4 ov = make_float4(o[i][0] * inv, o[i][1] * inv,
                                o[i][2] * inv, o[i][3] * inv);
        *(float4*)(AO + ((size_t)(b * SEQ + srow)) * D_MODEL + h * HEAD_DIM + tx * 4) = ov;
    }
}

// ---------------------------------------------------------------------------
extern "C" void kernel_launch(void* const* d_in, const int* in_sizes, int n_in,
                              void* d_out, int out_size)
{
    const float* x  = (const float*)d_in[0];
    const float* wq = (const float*)d_in[1];
    const float* bq = (const float*)d_in[2];
    const float* wk = (const float*)d_in[3];
    const float* bk = (const float*)d_in[4];
    const float* wv = (const float*)d_in[5];
    const float* bv = (const float*)d_in[6];
    const float* wo = (const float*)d_in[7];
    const float* bo = (const float*)d_in[8];

    float *Qp, *Kp, *Vp, *AOp;
    cudaGetSymbolAddress((void**)&Qp,  g_Q);
    cudaGetSymbolAddress((void**)&Kp,  g_K);
    cudaGetSymbolAddress((void**)&Vp,  g_V);
    cudaGetSymbolAddress((void**)&AOp, g_AO);

    const dim3 pg(D_MODEL / 128, MTOT / 128);   // (8, 64)

    gemm_tf32_kernel<true><<<pg, 256>>>(x, wq, bq, Qp);
    gemm_tf32_kernel<true><<<pg, 256>>>(x, wk, bk, Kp);
    gemm_tf32_kernel<true><<<pg, 256>>>(x, wv, bv, Vp);

    cudaFuncSetAttribute(flash_attn_kernel,
                         cudaFuncAttributeMaxDynamicSharedMemorySize, FA_SMEM);
    flash_attn_kernel<<<dim3(SEQ / 128, BATCH * NUM_HEADS), 256, FA_SMEM>>>(Qp, Kp, Vp, AOp);

    gemm_tf32_kernel<false><<<pg, 256>>>(AOp, wo, bo, (float*)d_out);
}

// round 7
// speedup vs baseline: 2.7500x; 1.8822x over previous
#include <cuda_runtime.h>

#define D_MODEL   1024
#define NUM_HEADS 16
#define HEAD_DIM  64
#define BATCH     4
#define SEQ       2048
#define MTOT      (BATCH * SEQ)

// Scratch (allocation-free: __device__ globals). 4 x 32 MB.
__device__ float g_Q [MTOT * D_MODEL];
__device__ float g_K [MTOT * D_MODEL];
__device__ float g_V [MTOT * D_MODEL];
__device__ float g_AO[MTOT * D_MODEL];

// ---------------------------------------------------------------------------
// common tf32 mma helpers (validated in R6: rel_err 4.3e-4)
// ---------------------------------------------------------------------------
__device__ __forceinline__ unsigned f2tf32(float x) {
    unsigned u;
    asm("cvt.rna.tf32.f32 %0, %1;" : "=r"(u) : "f"(x));
    return u;
}

__device__ __forceinline__ void mma_tf32(float c[4], const unsigned a[4],
                                         const unsigned b[2]) {
    asm volatile(
        "mma.sync.aligned.m16n8k8.row.col.f32.tf32.tf32.f32 "
        "{%0,%1,%2,%3}, {%4,%5,%6,%7}, {%8,%9}, {%0,%1,%2,%3};"
        : "+f"(c[0]), "+f"(c[1]), "+f"(c[2]), "+f"(c[3])
        : "r"(a[0]), "r"(a[1]), "r"(a[2]), "r"(a[3]), "r"(b[0]), "r"(b[1]));
}

// ---------------------------------------------------------------------------
// tf32 tensor-core GEMM (NT): C[M,N] = A[M,K] @ W[N,K]^T + bias[N]
// (unchanged from R6: ~100 TF/s, ~171 us per 8192x1024x1024)
// ---------------------------------------------------------------------------
#define GS 36   // smem row stride (words) for 32 k-columns

template <bool SCATTER>
__global__ __launch_bounds__(256)
void gemm_tf32_kernel(const float* __restrict__ A, const float* __restrict__ W,
                      const float* __restrict__ bias, float* __restrict__ C)
{
    const int K = D_MODEL;
    __shared__ unsigned As[128 * GS];
    __shared__ unsigned Ws[128 * GS];

    const int tid    = threadIdx.x;
    const int wid    = tid >> 5;
    const int lane   = tid & 31;
    const int gid    = lane >> 2;
    const int tig    = lane & 3;
    const int warp_m = wid >> 2;
    const int warp_n = wid & 3;
    const int m0     = blockIdx.y * 128;
    const int n0     = blockIdx.x * 128;

    const int grow = tid >> 1;
    const int gcol = (tid & 1) * 16;
    const float* aptr = A + (size_t)(m0 + grow) * K + gcol;
    const float* wptr = W + (size_t)(n0 + grow) * K + gcol;

    float acc[4][4][4];
#pragma unroll
    for (int i = 0; i < 4; i++)
#pragma unroll
        for (int j = 0; j < 4; j++)
#pragma unroll
            for (int r = 0; r < 4; r++) acc[i][j][r] = 0.f;

    float4 avr[4], wvr[4];
#pragma unroll
    for (int i = 0; i < 4; i++) {
        avr[i] = *(const float4*)(aptr + i * 4);
        wvr[i] = *(const float4*)(wptr + i * 4);
    }

    for (int k0 = 0; k0 < K; k0 += 32) {
        __syncthreads();
#pragma unroll
        for (int i = 0; i < 4; i++) {
            const int c = gcol + i * 4;
            As[grow * GS + c + 0] = f2tf32(avr[i].x);
            As[grow * GS + c + 1] = f2tf32(avr[i].y);
            As[grow * GS + c + 2] = f2tf32(avr[i].z);
            As[grow * GS + c + 3] = f2tf32(avr[i].w);
            Ws[grow * GS + c + 0] = f2tf32(wvr[i].x);
            Ws[grow * GS + c + 1] = f2tf32(wvr[i].y);
            Ws[grow * GS + c + 2] = f2tf32(wvr[i].z);
            Ws[grow * GS + c + 3] = f2tf32(wvr[i].w);
        }
        __syncthreads();

        if (k0 + 32 < K) {
#pragma unroll
            for (int i = 0; i < 4; i++) {
                avr[i] = *(const float4*)(aptr + k0 + 32 + i * 4);
                wvr[i] = *(const float4*)(wptr + k0 + 32 + i * 4);
            }
        }

#pragma unroll
        for (int k8 = 0; k8 < 4; k8++) {
            const int kk = k8 * 8;
            unsigned a[4][4], b[4][2];
#pragma unroll
            for (int mt = 0; mt < 4; mt++) {
                const int m = warp_m * 64 + mt * 16 + gid;
                a[mt][0] = As[(m)     * GS + kk + tig];
                a[mt][1] = As[(m + 8) * GS + kk + tig];
                a[mt][2] = As[(m)     * GS + kk + tig + 4];
                a[mt][3] = As[(m + 8) * GS + kk + tig + 4];
            }
#pragma unroll
            for (int nt = 0; nt < 4; nt++) {
                const int n = warp_n * 32 + nt * 8 + gid;
                b[nt][0] = Ws[n * GS + kk + tig];
                b[nt][1] = Ws[n * GS + kk + tig + 4];
            }
#pragma unroll
            for (int mt = 0; mt < 4; mt++)
#pragma unroll
                for (int nt = 0; nt < 4; nt++)
                    mma_tf32(acc[mt][nt], a[mt], b[nt]);
        }
    }

#pragma unroll
    for (int nt = 0; nt < 4; nt++) {
        const int n  = n0 + warp_n * 32 + nt * 8 + tig * 2;
        const float b0 = bias[n], b1 = bias[n + 1];
#pragma unroll
        for (int mt = 0; mt < 4; mt++) {
            const int m = m0 + warp_m * 64 + mt * 16 + gid;
            float2 v0 = make_float2(acc[mt][nt][0] + b0, acc[mt][nt][1] + b1);
            float2 v1 = make_float2(acc[mt][nt][2] + b0, acc[mt][nt][3] + b1);
            if (SCATTER) {
                const int h  = n >> 6;
                const int hd = n & 63;
                const int bb = m >> 11;
                const int s  = m & (SEQ - 1);
                float* p0 = C + ((size_t)((bb * NUM_HEADS + h) * SEQ + s))     * HEAD_DIM + hd;
                float* p1 = C + ((size_t)((bb * NUM_HEADS + h) * SEQ + s + 8)) * HEAD_DIM + hd;
                *(float2*)p0 = v0;
                *(float2*)p1 = v1;
            } else {
                *(float2*)(C + (size_t)m * D_MODEL + n)       = v0;
                *(float2*)(C + (size_t)(m + 8) * D_MODEL + n) = v1;
            }
        }
    }
}

// ---------------------------------------------------------------------------
// Flash attention v3: tf32 tensor cores for QK^T and PV, fp32 softmax.
// Br = Bc = 128, Hd = 64, 256 threads = 8 warps.
// Warp w owns S rows [w*16, w*16+16) x all 128 cols -> softmax row stats
// reduce inside the 4-thread fragment group (shfl xor 1,2 only).
// Smem strides chosen so every fragment load hits 32 distinct banks:
//   Q,K: stride 68 (addr = 4*gid + tig + const)
//   V:   natural [kv][hd], stride 72 (addr = 8*tig + gid + const)
//   P:   stride 132 (addr = 4*gid + tig + const)
// P hand-off is warp-private (each warp writes/reads only its own 16 rows)
// -> __syncwarp() instead of a CTA barrier.
// ---------------------------------------------------------------------------
#define FQS 68
#define FKS 68
#define FVS 72
#define FPS 132
#define FA_SMEM ((128*FQS + 128*FKS + 128*FVS + 128*FPS) * 4)

__global__ __launch_bounds__(256, 1)
void flash_attn_tc_kernel(const float* __restrict__ Q, const float* __restrict__ K,
                          const float* __restrict__ V, float* __restrict__ AO)
{
    extern __shared__ unsigned smu[];
    unsigned* Qs = smu;                       // [128][68] tf32
    unsigned* Ks = Qs + 128 * FQS;            // [128][68] tf32
    unsigned* Vs = Ks + 128 * FKS;            // [128][72] tf32 (natural layout)
    unsigned* Ps = Vs + 128 * FVS;            // [128][132] tf32

    const int tid  = threadIdx.x;
    const int w    = tid >> 5;
    const int lane = tid & 31;
    const int gid  = lane >> 2;
    const int tig  = lane & 3;
    const int bh   = blockIdx.y;
    const int q0   = blockIdx.x * 128;
    const float scale = 0.125f;               // HEAD_DIM^-0.5

    const float* Qb = Q + (size_t)bh * SEQ * HEAD_DIM;
    const float* Kb = K + (size_t)bh * SEQ * HEAD_DIM;
    const float* Vb = V + (size_t)bh * SEQ * HEAD_DIM;

    // Load Q tile (128x64), pre-scaled, tf32-rounded.
#pragma unroll
    for (int it = 0; it < 8; it++) {
        int idx = tid + it * 256;
        int r   = idx >> 4;
        int c4  = (idx & 15) * 4;
        float4 qv = *(const float4*)(Qb + (size_t)(q0 + r) * HEAD_DIM + c4);
        Qs[r * FQS + c4 + 0] = f2tf32(qv.x * scale);
        Qs[r * FQS + c4 + 1] = f2tf32(qv.y * scale);
        Qs[r * FQS + c4 + 2] = f2tf32(qv.z * scale);
        Qs[r * FQS + c4 + 3] = f2tf32(qv.w * scale);
    }

    const int r0 = w * 16 + gid;              // this thread's upper S row

    float m0v = -1e30f, m1v = -1e30f, l0 = 0.f, l1 = 0.f;
    float oacc[8][4];
#pragma unroll
    for (int nt = 0; nt < 8; nt++)
#pragma unroll
        for (int r = 0; r < 4; r++) oacc[nt][r] = 0.f;

    for (int kv0 = 0; kv0 < SEQ; kv0 += 128) {
        __syncthreads();   // all warps done reading Ks/Vs of previous tile
#pragma unroll
        for (int it = 0; it < 8; it++) {
            int idx = tid + it * 256;
            int r   = idx >> 4;
            int c4  = (idx & 15) * 4;
            float4 kv4 = *(const float4*)(Kb + (size_t)(kv0 + r) * HEAD_DIM + c4);
            Ks[r * FKS + c4 + 0] = f2tf32(kv4.x);
            Ks[r * FKS + c4 + 1] = f2tf32(kv4.y);
            Ks[r * FKS + c4 + 2] = f2tf32(kv4.z);
            Ks[r * FKS + c4 + 3] = f2tf32(kv4.w);
            float4 vv4 = *(const float4*)(Vb + (size_t)(kv0 + r) * HEAD_DIM + c4);
            Vs[r * FVS + c4 + 0] = f2tf32(vv4.x);
            Vs[r * FVS + c4 + 1] = f2tf32(vv4.y);
            Vs[r * FVS + c4 + 2] = f2tf32(vv4.z);
            Vs[r * FVS + c4 + 3] = f2tf32(vv4.w);
        }
        __syncthreads();

        // ---- S = Q K^T : warp computes 16 rows x 128 cols ----
        float sacc[16][4];
#pragma unroll
        for (int nt = 0; nt < 16; nt++)
#pragma unroll
            for (int r = 0; r < 4; r++) sacc[nt][r] = 0.f;

#pragma unroll
        for (int kk = 0; kk < 64; kk += 8) {
            unsigned a[4];
            a[0] = Qs[(r0)     * FQS + kk + tig];
            a[1] = Qs[(r0 + 8) * FQS + kk + tig];
            a[2] = Qs[(r0)     * FQS + kk + tig + 4];
            a[3] = Qs[(r0 + 8) * FQS + kk + tig + 4];
#pragma unroll
            for (int nt = 0; nt < 16; nt++) {
                const int n = nt * 8 + gid;
                unsigned b[2];
                b[0] = Ks[n * FKS + kk + tig];
                b[1] = Ks[n * FKS + kk + tig + 4];
                mma_tf32(sacc[nt], a, b);
            }
        }

        // ---- online softmax (rows r0 via c0/c1, r0+8 via c2/c3) ----
        float rm0 = -1e30f, rm1 = -1e30f;
#pragma unroll
        for (int nt = 0; nt < 16; nt++) {
            rm0 = fmaxf(rm0, fmaxf(sacc[nt][0], sacc[nt][1]));
            rm1 = fmaxf(rm1, fmaxf(sacc[nt][2], sacc[nt][3]));
        }
        rm0 = fmaxf(rm0, __shfl_xor_sync(0xffffffffu, rm0, 1));
        rm0 = fmaxf(rm0, __shfl_xor_sync(0xffffffffu, rm0, 2));
        rm1 = fmaxf(rm1, __shfl_xor_sync(0xffffffffu, rm1, 1));
        rm1 = fmaxf(rm1, __shfl_xor_sync(0xffffffffu, rm1, 2));

        const float mn0 = fmaxf(m0v, rm0);
        const float mn1 = fmaxf(m1v, rm1);
        const float al0 = __expf(m0v - mn0);
        const float al1 = __expf(m1v - mn1);
        m0v = mn0; m1v = mn1;

        float rs0 = 0.f, rs1 = 0.f;
#pragma unroll
        for (int nt = 0; nt < 16; nt++) {
            float p0 = __expf(sacc[nt][0] - mn0);
            float p1 = __expf(sacc[nt][1] - mn0);
            float p2 = __expf(sacc[nt][2] - mn1);
            float p3 = __expf(sacc[nt][3] - mn1);
            rs0 += p0 + p1;
            rs1 += p2 + p3;
            uint2 u01 = make_uint2(f2tf32(p0), f2tf32(p1));
            uint2 u23 = make_uint2(f2tf32(p2), f2tf32(p3));
            *(uint2*)&Ps[(r0)     * FPS + nt * 8 + 2 * tig] = u01;
            *(uint2*)&Ps[(r0 + 8) * FPS + nt * 8 + 2 * tig] = u23;
        }
        rs0 += __shfl_xor_sync(0xffffffffu, rs0, 1);
        rs0 += __shfl_xor_sync(0xffffffffu, rs0, 2);
        rs1 += __shfl_xor_sync(0xffffffffu, rs1, 1);
        rs1 += __shfl_xor_sync(0xffffffffu, rs1, 2);
        l0 = l0 * al0 + rs0;
        l1 = l1 * al1 + rs1;

#pragma unroll
        for (int nt = 0; nt < 8; nt++) {
            oacc[nt][0] *= al0; oacc[nt][1] *= al0;
            oacc[nt][2] *= al1; oacc[nt][3] *= al1;
        }
        __syncwarp();   // warp-private P rows: warp sync suffices

        // ---- O += P V : 16 rows x 64 cols per warp, k = 128 ----
#pragma unroll
        for (int kk = 0; kk < 128; kk += 8) {
            unsigned a[4];
            a[0] = Ps[(r0)     * FPS + kk + tig];
            a[1] = Ps[(r0 + 8) * FPS + kk + tig];
            a[2] = Ps[(r0)     * FPS + kk + tig + 4];
            a[3] = Ps[(r0 + 8) * FPS + kk + tig + 4];
#pragma unroll
            for (int nt = 0; nt < 8; nt++) {
                const int n = nt * 8 + gid;
                unsigned b[2];
                b[0] = Vs[(kk + tig)     * FVS + n];
                b[1] = Vs[(kk + tig + 4) * FVS + n];
                mma_tf32(oacc[nt], a, b);
            }
        }
    }

    // Epilogue: normalize, write [B,S,D]
    const int b = bh >> 4;
    const int h = bh & 15;
    const float inv0 = 1.0f / l0;
    const float inv1 = 1.0f / l1;
#pragma unroll
    for (int nt = 0; nt < 8; nt++) {
        const int col = h * HEAD_DIM + nt * 8 + 2 * tig;
        float2 v0 = make_float2(oacc[nt][0] * inv0, oacc[nt][1] * inv0);
        float2 v1 = make_float2(oacc[nt][2] * inv1, oacc[nt][3] * inv1);
        *(float2*)(AO + (size_t)(b * SEQ + q0 + r0)     * D_MODEL + col) = v0;
        *(float2*)(AO + (size_t)(b * SEQ + q0 + r0 + 8) * D_MODEL + col) = v1;
    }
}

// ---------------------------------------------------------------------------
extern "C" void kernel_launch(void* const* d_in, const int* in_sizes, int n_in,
                              void* d_out, int out_size)
{
    const float* x  = (const float*)d_in[0];
    const float* wq = (const float*)d_in[1];
    const float* bq = (const float*)d_in[2];
    const float* wk = (const float*)d_in[3];
    const float* bk = (const float*)d_in[4];
    const float* wv = (const float*)d_in[5];
    const float* bv = (const float*)d_in[6];
    const float* wo = (const float*)d_in[7];
    const float* bo = (const float*)d_in[8];

    float *Qp, *Kp, *Vp, *AOp;
    cudaGetSymbolAddress((void**)&Qp,  g_Q);
    cudaGetSymbolAddress((void**)&Kp,  g_K);
    cudaGetSymbolAddress((void**)&Vp,  g_V);
    cudaGetSymbolAddress((void**)&AOp, g_AO);

    const dim3 pg(D_MODEL / 128, MTOT / 128);   // (8, 64)

    gemm_tf32_kernel<true><<<pg, 256>>>(x, wq, bq, Qp);
    gemm_tf32_kernel<true><<<pg, 256>>>(x, wk, bk, Kp);
    gemm_tf32_kernel<true><<<pg, 256>>>(x, wv, bv, Vp);

    cudaFuncSetAttribute(flash_attn_tc_kernel,
                         cudaFuncAttributeMaxDynamicSharedMemorySize, FA_SMEM);
    flash_attn_tc_kernel<<<dim3(SEQ / 128, BATCH * NUM_HEADS), 256, FA_SMEM>>>(Qp, Kp, Vp, AOp);

    gemm_tf32_kernel<false><<<pg, 256>>>(AOp, wo, bo, (float*)d_out);
}